// round 14
// baseline (speedup 1.0000x reference)
#include <cuda_runtime.h>
#include <cuda_fp16.h>

#define N_NODES 100000
#define N_EDGES 3200000
#define D 128
#define SCAN_B 1024
#define N_SBLK ((N_NODES + SCAN_B - 1) / SCAN_B)   // 98

// ---------------- static device scratch (no allocation allowed) ----------------
__device__ __half    g_Y[(size_t)N_NODES * D];   // F @ W^T in fp16  (25.6 MB)
__device__ unsigned  g_edge[N_EDGES];            // src<<15 | norm_q15 (12.8 MB)
__device__ int       g_rank[N_EDGES];            // within-node rank (12.8 MB)
__device__ int       g_cnt[N_NODES];             // histogram
__device__ int       g_off[N_NODES + 1];         // CSR offsets
__device__ int       g_bsum[N_SBLK];             // per-block sums
__device__ int       g_bpref[N_SBLK];            // exclusive prefix of block sums

// ---------------- host-side stream/event resources (created pre-main) ----------
struct HostRes {
    cudaStream_t s;
    cudaEvent_t  fork_ev, join_ev;
    void* cnt_addr = nullptr;
    HostRes() {
        cudaStreamCreateWithFlags(&s, cudaStreamNonBlocking);
        cudaEventCreateWithFlags(&fork_ev, cudaEventDisableTiming);
        cudaEventCreateWithFlags(&join_ev, cudaEventDisableTiming);
    }
};
static HostRes g_res;

// ---------------------------------------------------------------------------
// histogram of dst, 4 edges per thread (int4 loads, 4 atomics in flight),
// capturing each edge's within-node rank
// ---------------------------------------------------------------------------
__global__ __launch_bounds__(256) void hist_kernel(const int* __restrict__ dst) {
    int i = (blockIdx.x * blockDim.x + threadIdx.x) * 4;   // N_EDGES % 4 == 0
    if (i < N_EDGES) {
        int4 d4 = *(const int4*)(dst + i);
        int r0 = atomicAdd(&g_cnt[d4.x], 1);
        int r1 = atomicAdd(&g_cnt[d4.y], 1);
        int r2 = atomicAdd(&g_cnt[d4.z], 1);
        int r3 = atomicAdd(&g_cnt[d4.w], 1);
        *(int4*)(g_rank + i) = make_int4(r0, r1, r2, r3);
    }
}

// ---------------------------------------------------------------------------
// scan stage 1: per-block sums of g_cnt (98 blocks x 1024)
// ---------------------------------------------------------------------------
__global__ __launch_bounds__(SCAN_B) void blocksum_kernel() {
    __shared__ int sh[SCAN_B / 32];
    int idx = blockIdx.x * SCAN_B + threadIdx.x;
    int v = (idx < N_NODES) ? g_cnt[idx] : 0;
#pragma unroll
    for (int o = 16; o > 0; o >>= 1) v += __shfl_xor_sync(0xffffffffu, v, o);
    if ((threadIdx.x & 31) == 0) sh[threadIdx.x >> 5] = v;
    __syncthreads();
    if (threadIdx.x < 32) {
        int w = (threadIdx.x < SCAN_B / 32) ? sh[threadIdx.x] : 0;
#pragma unroll
        for (int o = 16; o > 0; o >>= 1) w += __shfl_xor_sync(0xffffffffu, w, o);
        if (threadIdx.x == 0) g_bsum[blockIdx.x] = w;
    }
}

// ---------------------------------------------------------------------------
// scan stage 2: exclusive scan of 98 block sums (one tiny block)
// ---------------------------------------------------------------------------
__global__ __launch_bounds__(128) void scan_bsum_kernel() {
    __shared__ int sh[128];
    int tid = threadIdx.x;
    int v = (tid < N_SBLK) ? g_bsum[tid] : 0;
    sh[tid] = v;
    __syncthreads();
    for (int o = 1; o < 128; o <<= 1) {
        int t = (tid >= o) ? sh[tid - o] : 0;
        __syncthreads();
        sh[tid] += t;
        __syncthreads();
    }
    if (tid < N_SBLK) g_bpref[tid] = sh[tid] - v;   // exclusive
}

// ---------------------------------------------------------------------------
// scan stage 3: per-block scan + block prefix -> g_off
// ---------------------------------------------------------------------------
__global__ __launch_bounds__(SCAN_B) void offsets_kernel() {
    __shared__ int sh[SCAN_B];
    int tid = threadIdx.x;
    int idx = blockIdx.x * SCAN_B + tid;
    int v = (idx < N_NODES) ? g_cnt[idx] : 0;
    sh[tid] = v;
    __syncthreads();
    for (int o = 1; o < SCAN_B; o <<= 1) {
        int t = (tid >= o) ? sh[tid - o] : 0;
        __syncthreads();
        sh[tid] += t;
        __syncthreads();
    }
    if (idx < N_NODES)
        g_off[idx] = g_bpref[blockIdx.x] + sh[tid] - v;
    if (idx == 0) g_off[N_NODES] = N_EDGES;
}

// ---------------------------------------------------------------------------
// fill CSR edge list WITHOUT atomics, 4 edges per thread (int4 loads, 4x MLP)
// pos = off[dst] + rank; packed word: (src << 15) | floor(norm * 32768)
// ---------------------------------------------------------------------------
__global__ __launch_bounds__(256) void fill_kernel(const int* __restrict__ src,
                                                   const int* __restrict__ dst,
                                                   const float* __restrict__ norm) {
    int i = (blockIdx.x * blockDim.x + threadIdx.x) * 4;   // N_EDGES % 4 == 0
    if (i < N_EDGES) {
        int4   d4 = *(const int4*)(dst + i);
        int4   s4 = *(const int4*)(src + i);
        float4 n4 = *(const float4*)(norm + i);
        int4   r4 = *(const int4*)(g_rank + i);

        int o0 = __ldg(&g_off[d4.x]);
        int o1 = __ldg(&g_off[d4.y]);
        int o2 = __ldg(&g_off[d4.z]);
        int o3 = __ldg(&g_off[d4.w]);

        unsigned q0 = (unsigned)(n4.x * 32768.0f); if (q0 > 32767u) q0 = 32767u;
        unsigned q1 = (unsigned)(n4.y * 32768.0f); if (q1 > 32767u) q1 = 32767u;
        unsigned q2 = (unsigned)(n4.z * 32768.0f); if (q2 > 32767u) q2 = 32767u;
        unsigned q3 = (unsigned)(n4.w * 32768.0f); if (q3 > 32767u) q3 = 32767u;

        g_edge[o0 + r4.x] = ((unsigned)s4.x << 15) | q0;
        g_edge[o1 + r4.y] = ((unsigned)s4.y << 15) | q1;
        g_edge[o2 + r4.z] = ((unsigned)s4.z << 15) | q2;
        g_edge[o3 + r4.w] = ((unsigned)s4.w << 15) | q3;
    }
}

// ---------------------------------------------------------------------------
// Y = F @ W^T   (fp32 compute, fp16 store); 128x128 tile, BK=16, 8x8/thread
// ---------------------------------------------------------------------------
__global__ __launch_bounds__(256) void gemm_kernel(const float* __restrict__ F,
                                                   const float* __restrict__ W) {
    const int BM = 128, BK = 16, TM = 8, TN = 8;
    __shared__ float Fs[BK][BM];
    __shared__ float Ws[BK][BM];

    const int tid = threadIdx.x;
    const int tn = (tid % 16) * TN;
    const int tm = (tid / 16) * TM;
    const int m0 = blockIdx.x * BM;

    float acc[TM][TN];
#pragma unroll
    for (int i = 0; i < TM; i++)
#pragma unroll
        for (int j = 0; j < TN; j++) acc[i][j] = 0.0f;

    for (int kt = 0; kt < D; kt += BK) {
#pragma unroll
        for (int l = 0; l < 2; l++) {
            int idx = tid * 2 + l;
            int m   = idx >> 2;
            int kq  = idx & 3;
            float4 v = make_float4(0.f, 0.f, 0.f, 0.f);
            if (m0 + m < N_NODES)
                v = *(const float4*)(F + (size_t)(m0 + m) * D + kt + kq * 4);
            Fs[kq * 4 + 0][m] = v.x;
            Fs[kq * 4 + 1][m] = v.y;
            Fs[kq * 4 + 2][m] = v.z;
            Fs[kq * 4 + 3][m] = v.w;
        }
#pragma unroll
        for (int l = 0; l < 2; l++) {
            int idx = tid * 2 + l;
            int c   = idx >> 2;
            int kq  = idx & 3;
            float4 v = *(const float4*)(W + (size_t)c * D + kt + kq * 4);
            Ws[kq * 4 + 0][c] = v.x;
            Ws[kq * 4 + 1][c] = v.y;
            Ws[kq * 4 + 2][c] = v.z;
            Ws[kq * 4 + 3][c] = v.w;
        }
        __syncthreads();

#pragma unroll
        for (int k = 0; k < BK; k++) {
            float rm[TM], rn[TN];
            float4 a0 = *(const float4*)&Fs[k][tm];
            float4 a1 = *(const float4*)&Fs[k][tm + 4];
            float4 b0 = *(const float4*)&Ws[k][tn];
            float4 b1 = *(const float4*)&Ws[k][tn + 4];
            rm[0] = a0.x; rm[1] = a0.y; rm[2] = a0.z; rm[3] = a0.w;
            rm[4] = a1.x; rm[5] = a1.y; rm[6] = a1.z; rm[7] = a1.w;
            rn[0] = b0.x; rn[1] = b0.y; rn[2] = b0.z; rn[3] = b0.w;
            rn[4] = b1.x; rn[5] = b1.y; rn[6] = b1.z; rn[7] = b1.w;
#pragma unroll
            for (int i = 0; i < TM; i++)
#pragma unroll
                for (int j = 0; j < TN; j++)
                    acc[i][j] = fmaf(rm[i], rn[j], acc[i][j]);
        }
        __syncthreads();
    }

#pragma unroll
    for (int i = 0; i < TM; i++) {
        int m = m0 + tm + i;
        if (m < N_NODES) {
            __half2 h[4];
#pragma unroll
            for (int j = 0; j < 4; j++)
                h[j] = __floats2half2_rn(acc[i][2 * j], acc[i][2 * j + 1]);
            *(uint4*)(g_Y + (size_t)m * D + tn) = *(uint4*)h;
        }
    }
}

// ---------------------------------------------------------------------------
// per-node reduction (R8/R11 proven form): one warp/node, half-warp covers a
// 256B Y row, lane owns 8 halfs (LDG.128); counted loop, 4 edge words + 4
// gathers batched per iteration; .cs on edges/out to keep Y in L2.
// ---------------------------------------------------------------------------
__device__ __forceinline__ void fma8(float acc[8], uint4 u, float n) {
    float2 f0 = __half22float2(*(__half2*)&u.x);
    float2 f1 = __half22float2(*(__half2*)&u.y);
    float2 f2 = __half22float2(*(__half2*)&u.z);
    float2 f3 = __half22float2(*(__half2*)&u.w);
    acc[0] = fmaf(n, f0.x, acc[0]); acc[1] = fmaf(n, f0.y, acc[1]);
    acc[2] = fmaf(n, f1.x, acc[2]); acc[3] = fmaf(n, f1.y, acc[3]);
    acc[4] = fmaf(n, f2.x, acc[4]); acc[5] = fmaf(n, f2.y, acc[5]);
    acc[6] = fmaf(n, f3.x, acc[6]); acc[7] = fmaf(n, f3.y, acc[7]);
}

__device__ __forceinline__ void edge_fma(float acc[8], const __half* Ycol, unsigned w) {
    unsigned s = w >> 15;
    float   n = (float)(w & 0x7FFFu) * (1.0f / 32768.0f);
    uint4   u = *(const uint4*)(Ycol + (size_t)s * D);
    fma8(acc, u, n);
}

__global__ __launch_bounds__(256) void reduce_kernel(float* __restrict__ out,
                                                     const float* __restrict__ bias) {
    int warp = (blockIdx.x * blockDim.x + threadIdx.x) >> 5;
    int lane = threadIdx.x & 31;
    if (warp >= N_NODES) return;

    int beg = __ldg(&g_off[warp]);
    int end = __ldg(&g_off[warp + 1]);

    int half = lane >> 4;
    int hl   = lane & 15;

    float acc[8] = {0.f, 0.f, 0.f, 0.f, 0.f, 0.f, 0.f, 0.f};
    const __half* Ycol = g_Y + hl * 8;

    int e = beg + half;
    for (; e + 6 < end; e += 8) {
        unsigned w0 = __ldcs(&g_edge[e]);
        unsigned w1 = __ldcs(&g_edge[e + 2]);
        unsigned w2 = __ldcs(&g_edge[e + 4]);
        unsigned w3 = __ldcs(&g_edge[e + 6]);
        unsigned s0 = w0 >> 15, s1 = w1 >> 15, s2 = w2 >> 15, s3 = w3 >> 15;
        uint4 u0 = *(const uint4*)(Ycol + (size_t)s0 * D);
        uint4 u1 = *(const uint4*)(Ycol + (size_t)s1 * D);
        uint4 u2 = *(const uint4*)(Ycol + (size_t)s2 * D);
        uint4 u3 = *(const uint4*)(Ycol + (size_t)s3 * D);
        fma8(acc, u0, (float)(w0 & 0x7FFFu) * (1.0f / 32768.0f));
        fma8(acc, u1, (float)(w1 & 0x7FFFu) * (1.0f / 32768.0f));
        fma8(acc, u2, (float)(w2 & 0x7FFFu) * (1.0f / 32768.0f));
        fma8(acc, u3, (float)(w3 & 0x7FFFu) * (1.0f / 32768.0f));
    }
    for (; e < end; e += 2)
        edge_fma(acc, Ycol, __ldcs(&g_edge[e]));

#pragma unroll
    for (int j = 0; j < 8; j++)
        acc[j] += __shfl_xor_sync(0xffffffffu, acc[j], 16);

    if (half == 0) {
        const float4* b4 = (const float4*)bias;
        float4 b0 = b4[hl * 2], b1 = b4[hl * 2 + 1];
        float4* o = (float4*)(out + (size_t)warp * D + hl * 8);
        __stcs(o,     make_float4(acc[0] + b0.x, acc[1] + b0.y,
                                  acc[2] + b0.z, acc[3] + b0.w));
        __stcs(o + 1, make_float4(acc[4] + b1.x, acc[5] + b1.y,
                                  acc[6] + b1.z, acc[7] + b1.w));
    }
}

// ---------------------------------------------------------------------------
extern "C" void kernel_launch(void* const* d_in, const int* in_sizes, int n_in,
                              void* d_out, int out_size) {
    const float* features = (const float*)d_in[0];
    const float* norm     = (const float*)d_in[1];
    const int*   src      = (const int*)d_in[2];
    const int*   dst      = (const int*)d_in[3];
    const float* weight   = (const float*)d_in[4];
    const float* bias     = (const float*)d_in[5];
    float*       out      = (float*)d_out;

    if (!g_res.cnt_addr) cudaGetSymbolAddress(&g_res.cnt_addr, g_cnt);

    // Fork: GEMM on side stream, concurrent with the CSR sort pipeline.
    cudaEventRecord(g_res.fork_ev, 0);
    cudaStreamWaitEvent(g_res.s, g_res.fork_ev, 0);
    gemm_kernel<<<(N_NODES + 127) / 128, 256, 0, g_res.s>>>(features, weight);
    cudaEventRecord(g_res.join_ev, g_res.s);

    // Main stream: counting sort by dst (rank captured in hist; fill atomic-free)
    cudaMemsetAsync(g_res.cnt_addr, 0, N_NODES * sizeof(int), 0);
    hist_kernel<<<(N_EDGES / 4 + 255) / 256, 256>>>(dst);
    blocksum_kernel<<<N_SBLK, SCAN_B>>>();
    scan_bsum_kernel<<<1, 128>>>();
    offsets_kernel<<<N_SBLK, SCAN_B>>>();
    fill_kernel<<<(N_EDGES / 4 + 255) / 256, 256>>>(src, dst, norm);

    // Join, then reduce (one warp per node)
    cudaStreamWaitEvent(0, g_res.join_ev, 0);
    long long total_threads = (long long)N_NODES * 32;
    reduce_kernel<<<(int)((total_threads + 255) / 256), 256>>>(out, bias);
}

// round 16
// speedup vs baseline: 1.1962x; 1.1962x over previous
#include <cuda_runtime.h>
#include <cuda_fp16.h>
#include <cstdint>

#define N_NODES 100000
#define N_EDGES 3200000
#define D 128
#define SCAN_B 1024
#define N_SBLK ((N_NODES + SCAN_B - 1) / SCAN_B)   // 98

// ---------------- static device scratch (no allocation allowed) ----------------
__device__ __half    g_Y[(size_t)N_NODES * D];   // F @ W^T in fp16  (25.6 MB)
__device__ unsigned  g_edge[N_EDGES];            // src<<15 | norm_q15 (12.8 MB)
__device__ int       g_rank[N_EDGES];            // within-node rank (12.8 MB)
__device__ int       g_cnt[N_NODES];             // histogram
__device__ int       g_off[N_NODES + 1];         // CSR offsets

// ---------------- host-side stream/event resources (created pre-main) ----------
struct HostRes {
    cudaStream_t s;
    cudaEvent_t  fork_ev, join_ev;
    void* cnt_addr = nullptr;
    HostRes() {
        cudaStreamCreateWithFlags(&s, cudaStreamNonBlocking);
        cudaEventCreateWithFlags(&fork_ev, cudaEventDisableTiming);
        cudaEventCreateWithFlags(&join_ev, cudaEventDisableTiming);
    }
};
static HostRes g_res;

// ---------------------------------------------------------------------------
// histogram of dst, 4 edges per thread (int4 loads, 4 atomics in flight),
// capturing each edge's within-node rank
// ---------------------------------------------------------------------------
__global__ __launch_bounds__(256) void hist_kernel(const int* __restrict__ dst) {
    int i = (blockIdx.x * blockDim.x + threadIdx.x) * 4;   // N_EDGES % 4 == 0
    if (i < N_EDGES) {
        int4 d4 = *(const int4*)(dst + i);
        int r0 = atomicAdd(&g_cnt[d4.x], 1);
        int r1 = atomicAdd(&g_cnt[d4.y], 1);
        int r2 = atomicAdd(&g_cnt[d4.z], 1);
        int r3 = atomicAdd(&g_cnt[d4.w], 1);
        *(int4*)(g_rank + i) = make_int4(r0, r1, r2, r3);
    }
}

// ---------------------------------------------------------------------------
// single-kernel scan: each block sums its preceding g_cnt range (block
// prefix), then local Hillis-Steele scan -> g_off
// ---------------------------------------------------------------------------
__global__ __launch_bounds__(SCAN_B) void offsets_kernel() {
    __shared__ int sh[SCAN_B];
    __shared__ int red[32];
    __shared__ int s_bpref;

    int tid = threadIdx.x;
    int start = blockIdx.x * SCAN_B;

    // 1) block prefix: sum of g_cnt[0 .. start)
    int pre = 0;
    for (int i = tid; i < start; i += SCAN_B) pre += g_cnt[i];
#pragma unroll
    for (int o = 16; o > 0; o >>= 1) pre += __shfl_xor_sync(0xffffffffu, pre, o);
    if ((tid & 31) == 0) red[tid >> 5] = pre;
    __syncthreads();
    if (tid < 32) {
        int w = (tid < SCAN_B / 32) ? red[tid] : 0;
#pragma unroll
        for (int o = 16; o > 0; o >>= 1) w += __shfl_xor_sync(0xffffffffu, w, o);
        if (tid == 0) s_bpref = w;
    }

    // 2) local scan of this block's 1024 counters
    int idx = start + tid;
    int v = (idx < N_NODES) ? g_cnt[idx] : 0;
    sh[tid] = v;
    __syncthreads();
    for (int o = 1; o < SCAN_B; o <<= 1) {
        int t = (tid >= o) ? sh[tid - o] : 0;
        __syncthreads();
        sh[tid] += t;
        __syncthreads();
    }
    if (idx < N_NODES)
        g_off[idx] = s_bpref + sh[tid] - v;   // global exclusive prefix
    if (idx == 0) g_off[N_NODES] = N_EDGES;
}

// ---------------------------------------------------------------------------
// fill CSR edge list WITHOUT atomics, 4 edges per thread (int4 loads, 4x MLP)
// pos = off[dst] + rank; packed word: (src << 15) | floor(norm * 32768)
// ---------------------------------------------------------------------------
__global__ __launch_bounds__(256) void fill_kernel(const int* __restrict__ src,
                                                   const int* __restrict__ dst,
                                                   const float* __restrict__ norm) {
    int i = (blockIdx.x * blockDim.x + threadIdx.x) * 4;   // N_EDGES % 4 == 0
    if (i < N_EDGES) {
        int4   d4 = *(const int4*)(dst + i);
        int4   s4 = *(const int4*)(src + i);
        float4 n4 = *(const float4*)(norm + i);
        int4   r4 = *(const int4*)(g_rank + i);

        int o0 = __ldg(&g_off[d4.x]);
        int o1 = __ldg(&g_off[d4.y]);
        int o2 = __ldg(&g_off[d4.z]);
        int o3 = __ldg(&g_off[d4.w]);

        unsigned q0 = (unsigned)(n4.x * 32768.0f); if (q0 > 32767u) q0 = 32767u;
        unsigned q1 = (unsigned)(n4.y * 32768.0f); if (q1 > 32767u) q1 = 32767u;
        unsigned q2 = (unsigned)(n4.z * 32768.0f); if (q2 > 32767u) q2 = 32767u;
        unsigned q3 = (unsigned)(n4.w * 32768.0f); if (q3 > 32767u) q3 = 32767u;

        g_edge[o0 + r4.x] = ((unsigned)s4.x << 15) | q0;
        g_edge[o1 + r4.y] = ((unsigned)s4.y << 15) | q1;
        g_edge[o2 + r4.z] = ((unsigned)s4.z << 15) | q2;
        g_edge[o3 + r4.w] = ((unsigned)s4.w << 15) | q3;
    }
}

// ---------------------------------------------------------------------------
// Y = F @ W^T via tensor cores: mma.sync m16n8k16 fp16 inputs, fp32 accum.
// Block = 128 M-rows, 8 warps (one 16-row strip each), full N=128 per warp.
// W staged in smem as fp16 (padded rows -> conflict-free B-frag LDS);
// A fragments loaded directly from global F with fp32->fp16 convert.
// ---------------------------------------------------------------------------
__device__ __forceinline__ uint32_t pack_h2(float2 f) {
    __half2 h = __floats2half2_rn(f.x, f.y);
    return *(uint32_t*)&h;
}

__global__ __launch_bounds__(256) void gemm_kernel(const float* __restrict__ F,
                                                   const float* __restrict__ W) {
    __shared__ __half Wsm[128][136];   // 136-half rows: B-frag LDS bank = 4n+tg

    int tid = threadIdx.x;
    // Stage W (128x128 fp32 -> fp16)
    for (int idx = tid; idx < 128 * 32; idx += 256) {
        int n  = idx >> 5;
        int c4 = idx & 31;
        float4 w4 = ((const float4*)W)[n * 32 + c4];
        *(__half2*)&Wsm[n][c4 * 4]     = __floats2half2_rn(w4.x, w4.y);
        *(__half2*)&Wsm[n][c4 * 4 + 2] = __floats2half2_rn(w4.z, w4.w);
    }
    __syncthreads();

    int wid  = tid >> 5;
    int lane = tid & 31;
    int g    = lane >> 2;      // 0..7
    int tg   = lane & 3;       // 0..3

    int rowA = blockIdx.x * 128 + wid * 16 + g;   // rows rowA and rowA+8
    bool ok0 = rowA < N_NODES;
    bool ok1 = (rowA + 8) < N_NODES;
    const float* Fr0 = F + (size_t)rowA * D;
    const float* Fr1 = Fr0 + (size_t)8 * D;

    float acc[16][4];
#pragma unroll
    for (int j = 0; j < 16; j++)
#pragma unroll
        for (int c = 0; c < 4; c++) acc[j][c] = 0.0f;

#pragma unroll
    for (int ks = 0; ks < 8; ks++) {
        int kb = ks * 16;
        float2 z = make_float2(0.f, 0.f);
        float2 f00 = ok0 ? *(const float2*)(Fr0 + kb + 2 * tg)     : z;
        float2 f10 = ok1 ? *(const float2*)(Fr1 + kb + 2 * tg)     : z;
        float2 f01 = ok0 ? *(const float2*)(Fr0 + kb + 2 * tg + 8) : z;
        float2 f11 = ok1 ? *(const float2*)(Fr1 + kb + 2 * tg + 8) : z;
        uint32_t a0 = pack_h2(f00);   // (rowA,   k=kb+2tg..+1)
        uint32_t a1 = pack_h2(f10);   // (rowA+8, same k)
        uint32_t a2 = pack_h2(f01);   // (rowA,   k+8)
        uint32_t a3 = pack_h2(f11);   // (rowA+8, k+8)

#pragma unroll
        for (int j = 0; j < 16; j++) {
            int n = j * 8 + g;
            uint32_t b0 = *(const uint32_t*)&Wsm[n][kb + 2 * tg];
            uint32_t b1 = *(const uint32_t*)&Wsm[n][kb + 2 * tg + 8];
            asm volatile(
                "mma.sync.aligned.m16n8k16.row.col.f32.f16.f16.f32 "
                "{%0,%1,%2,%3}, {%4,%5,%6,%7}, {%8,%9}, {%0,%1,%2,%3};"
                : "+f"(acc[j][0]), "+f"(acc[j][1]), "+f"(acc[j][2]), "+f"(acc[j][3])
                : "r"(a0), "r"(a1), "r"(a2), "r"(a3), "r"(b0), "r"(b1));
        }
    }

    // Store Y (fp16): c0,c1 -> (rowA, n+2tg..+1); c2,c3 -> (rowA+8, same cols)
#pragma unroll
    for (int j = 0; j < 16; j++) {
        int n = j * 8 + 2 * tg;
        if (ok0)
            *(__half2*)(g_Y + (size_t)rowA * D + n) =
                __floats2half2_rn(acc[j][0], acc[j][1]);
        if (ok1)
            *(__half2*)(g_Y + (size_t)(rowA + 8) * D + n) =
                __floats2half2_rn(acc[j][2], acc[j][3]);
    }
}

// ---------------------------------------------------------------------------
// per-node reduction (R8/R11 proven form): one warp/node, half-warp covers a
// 256B Y row, lane owns 8 halfs (LDG.128); counted loop, 4 edge words + 4
// gathers batched per iteration; .cs on edges/out to keep Y in L2.
// ---------------------------------------------------------------------------
__device__ __forceinline__ void fma8(float acc[8], uint4 u, float n) {
    float2 f0 = __half22float2(*(__half2*)&u.x);
    float2 f1 = __half22float2(*(__half2*)&u.y);
    float2 f2 = __half22float2(*(__half2*)&u.z);
    float2 f3 = __half22float2(*(__half2*)&u.w);
    acc[0] = fmaf(n, f0.x, acc[0]); acc[1] = fmaf(n, f0.y, acc[1]);
    acc[2] = fmaf(n, f1.x, acc[2]); acc[3] = fmaf(n, f1.y, acc[3]);
    acc[4] = fmaf(n, f2.x, acc[4]); acc[5] = fmaf(n, f2.y, acc[5]);
    acc[6] = fmaf(n, f3.x, acc[6]); acc[7] = fmaf(n, f3.y, acc[7]);
}

__device__ __forceinline__ void edge_fma(float acc[8], const __half* Ycol, unsigned w) {
    unsigned s = w >> 15;
    float   n = (float)(w & 0x7FFFu) * (1.0f / 32768.0f);
    uint4   u = *(const uint4*)(Ycol + (size_t)s * D);
    fma8(acc, u, n);
}

__global__ __launch_bounds__(256) void reduce_kernel(float* __restrict__ out,
                                                     const float* __restrict__ bias) {
    int warp = (blockIdx.x * blockDim.x + threadIdx.x) >> 5;
    int lane = threadIdx.x & 31;
    if (warp >= N_NODES) return;

    int beg = __ldg(&g_off[warp]);
    int end = __ldg(&g_off[warp + 1]);

    int half = lane >> 4;
    int hl   = lane & 15;

    float acc[8] = {0.f, 0.f, 0.f, 0.f, 0.f, 0.f, 0.f, 0.f};
    const __half* Ycol = g_Y + hl * 8;

    int e = beg + half;
    for (; e + 6 < end; e += 8) {
        unsigned w0 = __ldcs(&g_edge[e]);
        unsigned w1 = __ldcs(&g_edge[e + 2]);
        unsigned w2 = __ldcs(&g_edge[e + 4]);
        unsigned w3 = __ldcs(&g_edge[e + 6]);
        unsigned s0 = w0 >> 15, s1 = w1 >> 15, s2 = w2 >> 15, s3 = w3 >> 15;
        uint4 u0 = *(const uint4*)(Ycol + (size_t)s0 * D);
        uint4 u1 = *(const uint4*)(Ycol + (size_t)s1 * D);
        uint4 u2 = *(const uint4*)(Ycol + (size_t)s2 * D);
        uint4 u3 = *(const uint4*)(Ycol + (size_t)s3 * D);
        fma8(acc, u0, (float)(w0 & 0x7FFFu) * (1.0f / 32768.0f));
        fma8(acc, u1, (float)(w1 & 0x7FFFu) * (1.0f / 32768.0f));
        fma8(acc, u2, (float)(w2 & 0x7FFFu) * (1.0f / 32768.0f));
        fma8(acc, u3, (float)(w3 & 0x7FFFu) * (1.0f / 32768.0f));
    }
    for (; e < end; e += 2)
        edge_fma(acc, Ycol, __ldcs(&g_edge[e]));

#pragma unroll
    for (int j = 0; j < 8; j++)
        acc[j] += __shfl_xor_sync(0xffffffffu, acc[j], 16);

    if (half == 0) {
        const float4* b4 = (const float4*)bias;
        float4 b0 = b4[hl * 2], b1 = b4[hl * 2 + 1];
        float4* o = (float4*)(out + (size_t)warp * D + hl * 8);
        __stcs(o,     make_float4(acc[0] + b0.x, acc[1] + b0.y,
                                  acc[2] + b0.z, acc[3] + b0.w));
        __stcs(o + 1, make_float4(acc[4] + b1.x, acc[5] + b1.y,
                                  acc[6] + b1.z, acc[7] + b1.w));
    }
}

// ---------------------------------------------------------------------------
extern "C" void kernel_launch(void* const* d_in, const int* in_sizes, int n_in,
                              void* d_out, int out_size) {
    const float* features = (const float*)d_in[0];
    const float* norm     = (const float*)d_in[1];
    const int*   src      = (const int*)d_in[2];
    const int*   dst      = (const int*)d_in[3];
    const float* weight   = (const float*)d_in[4];
    const float* bias     = (const float*)d_in[5];
    float*       out      = (float*)d_out;

    if (!g_res.cnt_addr) cudaGetSymbolAddress(&g_res.cnt_addr, g_cnt);

    // Fork: tensor-core GEMM on side stream, concurrent with the sort pipeline.
    cudaEventRecord(g_res.fork_ev, 0);
    cudaStreamWaitEvent(g_res.s, g_res.fork_ev, 0);
    gemm_kernel<<<(N_NODES + 127) / 128, 256, 0, g_res.s>>>(features, weight);
    cudaEventRecord(g_res.join_ev, g_res.s);

    // Main stream: counting sort by dst (rank captured in hist; 1-kernel scan)
    cudaMemsetAsync(g_res.cnt_addr, 0, N_NODES * sizeof(int), 0);
    hist_kernel<<<(N_EDGES / 4 + 255) / 256, 256>>>(dst);
    offsets_kernel<<<N_SBLK, SCAN_B>>>();
    fill_kernel<<<(N_EDGES / 4 + 255) / 256, 256>>>(src, dst, norm);

    // Join, then reduce (one warp per node)
    cudaStreamWaitEvent(0, g_res.join_ev, 0);
    long long total_threads = (long long)N_NODES * 32;
    reduce_kernel<<<(int)((total_threads + 255) / 256), 256>>>(out, bias);
}